// round 1
// baseline (speedup 1.0000x reference)
#include <cuda_runtime.h>
#include <cstddef>

// Problem dims (fixed by the dataset)
constexpr int B = 4, C = 16, H = 512, W = 960;
constexpr int HW   = H * W;
constexpr int NPIX = B * HW;           // 1,966,080
constexpr int SC   = 20;               // scratch channels: 16 vals + 1 metric + pad to 16B align

// Accumulation scratch: [B,H,W,SC] channel-last, 16B-aligned per pixel.
__device__ __align__(16) float g_scratch[(size_t)NPIX * SC];

__device__ __forceinline__ void red_add_v4(float* p, float a, float b, float c, float d) {
    asm volatile("red.global.add.v4.f32 [%0], {%1, %2, %3, %4};"
                 :: "l"(p), "f"(a), "f"(b), "f"(c), "f"(d) : "memory");
}
__device__ __forceinline__ void red_add_f32(float* p, float a) {
    asm volatile("red.global.add.f32 [%0], %1;" :: "l"(p), "f"(a) : "memory");
}

__global__ void __launch_bounds__(256)
splat_kernel(const float* __restrict__ in,
             const float* __restrict__ flow,
             const float* __restrict__ metric) {
    int idx = blockIdx.x * blockDim.x + threadIdx.x;
    if (idx >= NPIX) return;
    int b = idx / HW;
    int p = idx - b * HW;
    int y = p / W;
    int x = p - y * W;

    const float fx = (float)x + flow[(size_t)b * 2 * HW + p];
    const float fy = (float)y + flow[(size_t)b * 2 * HW + HW + p];
    const float m  = __expf(metric[idx]);

    const float x0f = floorf(fx), y0f = floorf(fy);
    const int   x0  = (int)x0f,   y0  = (int)y0f;
    const float wx1 = fx - x0f, wy1 = fy - y0f;
    const float wx0 = 1.0f - wx1, wy0 = 1.0f - wy1;

    // Pre-scale channel values by exp(metric)
    float v[16];
    const float* inp = in + (size_t)b * C * HW + p;
#pragma unroll
    for (int c = 0; c < 16; ++c) v[c] = inp[(size_t)c * HW] * m;

#pragma unroll
    for (int cy = 0; cy < 2; ++cy) {
        const int yi = y0 + cy;
        if (yi < 0 || yi >= H) continue;
        const float wy = cy ? wy1 : wy0;
#pragma unroll
        for (int cx = 0; cx < 2; ++cx) {
            const int xi = x0 + cx;
            if (xi < 0 || xi >= W) continue;
            const float w = wy * (cx ? wx1 : wx0);
            float* dst = g_scratch + ((size_t)b * HW + (size_t)yi * W + xi) * SC;
#pragma unroll
            for (int q = 0; q < 4; ++q) {
                red_add_v4(dst + q * 4,
                           v[q * 4 + 0] * w, v[q * 4 + 1] * w,
                           v[q * 4 + 2] * w, v[q * 4 + 3] * w);
            }
            red_add_f32(dst + 16, m * w);
        }
    }
}

__global__ void __launch_bounds__(256)
norm_kernel(float* __restrict__ out) {
    int idx = blockIdx.x * blockDim.x + threadIdx.x;
    if (idx >= NPIX) return;
    int b = idx / HW;
    int p = idx - b * HW;

    const float4* s = reinterpret_cast<const float4*>(g_scratch + (size_t)idx * SC);
    float4 a0 = s[0], a1 = s[1], a2 = s[2], a3 = s[3];
    float  nrm = g_scratch[(size_t)idx * SC + 16] + 1e-7f;
    float  inv = 1.0f / nrm;

    float* o = out + (size_t)b * C * HW + p;
    o[(size_t)0  * HW] = a0.x * inv;
    o[(size_t)1  * HW] = a0.y * inv;
    o[(size_t)2  * HW] = a0.z * inv;
    o[(size_t)3  * HW] = a0.w * inv;
    o[(size_t)4  * HW] = a1.x * inv;
    o[(size_t)5  * HW] = a1.y * inv;
    o[(size_t)6  * HW] = a1.z * inv;
    o[(size_t)7  * HW] = a1.w * inv;
    o[(size_t)8  * HW] = a2.x * inv;
    o[(size_t)9  * HW] = a2.y * inv;
    o[(size_t)10 * HW] = a2.z * inv;
    o[(size_t)11 * HW] = a2.w * inv;
    o[(size_t)12 * HW] = a3.x * inv;
    o[(size_t)13 * HW] = a3.y * inv;
    o[(size_t)14 * HW] = a3.z * inv;
    o[(size_t)15 * HW] = a3.w * inv;
}

extern "C" void kernel_launch(void* const* d_in, const int* in_sizes, int n_in,
                              void* d_out, int out_size) {
    const float* ten_in     = (const float*)d_in[0];
    const float* ten_flow   = (const float*)d_in[1];
    const float* ten_metric = (const float*)d_in[2];
    float* out = (float*)d_out;

    void* scratch_ptr = nullptr;
    cudaGetSymbolAddress(&scratch_ptr, g_scratch);
    cudaMemsetAsync(scratch_ptr, 0, (size_t)NPIX * SC * sizeof(float));

    const int threads = 256;
    const int blocks  = (NPIX + threads - 1) / threads;
    splat_kernel<<<blocks, threads>>>(ten_in, ten_flow, ten_metric);
    norm_kernel<<<blocks, threads>>>(out);
}

// round 2
// speedup vs baseline: 1.0681x; 1.0681x over previous
#include <cuda_runtime.h>
#include <cstddef>

// Problem dims (fixed by the dataset)
constexpr int B = 4, C = 16, H = 512, W = 960;
constexpr int HW   = H * W;
constexpr int NPIX = B * HW;           // 1,966,080

// Accumulation scratch, zero-initialized at module load.
// norm_kernel re-zeros after reading, so every kernel_launch call sees zeros.
__device__ __align__(16) float g_vals[(size_t)NPIX * 16];  // [pix][16ch], 64B rows
__device__ float g_met[(size_t)NPIX];                      // splatted exp(metric)

__device__ __forceinline__ void red_add_v4(float* p, float a, float b, float c, float d) {
    asm volatile("red.global.add.v4.f32 [%0], {%1, %2, %3, %4};"
                 :: "l"(p), "f"(a), "f"(b), "f"(c), "f"(d) : "memory");
}
__device__ __forceinline__ void red_add_f32(float* p, float a) {
    asm volatile("red.global.add.f32 [%0], %1;" :: "l"(p), "f"(a) : "memory");
}

__global__ void __launch_bounds__(256)
splat_kernel(const float* __restrict__ in,
             const float* __restrict__ flow,
             const float* __restrict__ metric) {
    int idx = blockIdx.x * blockDim.x + threadIdx.x;
    if (idx >= NPIX) return;
    int b = idx / HW;
    int p = idx - b * HW;
    int y = p / W;
    int x = p - y * W;

    const float fx = (float)x + flow[(size_t)b * 2 * HW + p];
    const float fy = (float)y + flow[(size_t)b * 2 * HW + HW + p];
    const float m  = __expf(metric[idx]);

    const float x0f = floorf(fx), y0f = floorf(fy);
    const int   x0  = (int)x0f,   y0  = (int)y0f;
    const float wx1 = fx - x0f, wy1 = fy - y0f;
    const float wx0 = 1.0f - wx1, wy0 = 1.0f - wy1;

    // Pre-scale channel values by exp(metric)
    float v[16];
    const float* inp = in + (size_t)b * C * HW + p;
#pragma unroll
    for (int c = 0; c < 16; ++c) v[c] = inp[(size_t)c * HW] * m;

#pragma unroll
    for (int cy = 0; cy < 2; ++cy) {
        const int yi = y0 + cy;
        if (yi < 0 || yi >= H) continue;
        const float wy = cy ? wy1 : wy0;
#pragma unroll
        for (int cx = 0; cx < 2; ++cx) {
            const int xi = x0 + cx;
            if (xi < 0 || xi >= W) continue;
            const float w = wy * (cx ? wx1 : wx0);
            const size_t d = (size_t)b * HW + (size_t)yi * W + xi;
            float* dst = g_vals + d * 16;
#pragma unroll
            for (int q = 0; q < 4; ++q) {
                red_add_v4(dst + q * 4,
                           v[q * 4 + 0] * w, v[q * 4 + 1] * w,
                           v[q * 4 + 2] * w, v[q * 4 + 3] * w);
            }
            red_add_f32(g_met + d, m * w);
        }
    }
}

__global__ void __launch_bounds__(256)
norm_kernel(float* __restrict__ out) {
    int idx = blockIdx.x * blockDim.x + threadIdx.x;
    if (idx >= NPIX) return;
    int b = idx / HW;
    int p = idx - b * HW;

    float4* s = reinterpret_cast<float4*>(g_vals + (size_t)idx * 16);
    float4 a0 = s[0], a1 = s[1], a2 = s[2], a3 = s[3];
    float  nrm = g_met[idx] + 1e-7f;
    float  inv = 1.0f / nrm;

    float* o = out + (size_t)b * C * HW + p;
    o[(size_t)0  * HW] = a0.x * inv;
    o[(size_t)1  * HW] = a0.y * inv;
    o[(size_t)2  * HW] = a0.z * inv;
    o[(size_t)3  * HW] = a0.w * inv;
    o[(size_t)4  * HW] = a1.x * inv;
    o[(size_t)5  * HW] = a1.y * inv;
    o[(size_t)6  * HW] = a1.z * inv;
    o[(size_t)7  * HW] = a1.w * inv;
    o[(size_t)8  * HW] = a2.x * inv;
    o[(size_t)9  * HW] = a2.y * inv;
    o[(size_t)10 * HW] = a2.z * inv;
    o[(size_t)11 * HW] = a2.w * inv;
    o[(size_t)12 * HW] = a3.x * inv;
    o[(size_t)13 * HW] = a3.y * inv;
    o[(size_t)14 * HW] = a3.z * inv;
    o[(size_t)15 * HW] = a3.w * inv;

    // Restore zeros for the next call (replaces the standalone memset pass).
    const float4 z = make_float4(0.f, 0.f, 0.f, 0.f);
    s[0] = z; s[1] = z; s[2] = z; s[3] = z;
    g_met[idx] = 0.0f;
}

extern "C" void kernel_launch(void* const* d_in, const int* in_sizes, int n_in,
                              void* d_out, int out_size) {
    const float* ten_in     = (const float*)d_in[0];
    const float* ten_flow   = (const float*)d_in[1];
    const float* ten_metric = (const float*)d_in[2];
    float* out = (float*)d_out;

    const int threads = 256;
    const int blocks  = (NPIX + threads - 1) / threads;
    splat_kernel<<<blocks, threads>>>(ten_in, ten_flow, ten_metric);
    norm_kernel<<<blocks, threads>>>(out);
}